// round 15
// baseline (speedup 1.0000x reference)
#include <cuda_runtime.h>
#include <cstdint>

#define NB   32
#define CCH  512
#define HWD  3136
#define LL   64
#define CTD  512
#define KTOT 576   // 561 padded to 576
#define NCH  25    // softmax chunks = ceil(3136/128)

// -------- scratch (device globals; no runtime allocation) --------
__device__ float g_tc[(size_t)NB * HWD * LL];      // RAW scaled logits, layout (n, hw, l)
__device__ float g_part[NB * NCH * LL * 2];        // per-CTA online-softmax (m, s)
__device__ float g_Ap[4][(size_t)NB * CTD * LL];   // split-K partials of A (n, c, l)
__device__ float g_pcp[NB * LL * 49];              // pos-encoder conv output (n, l, 49)
__device__ float g_B[(size_t)NB * KTOT * LL];      // concat [tokens0; pos; zeros] (n, 576, l)
__device__ float g_wtcT[CCH * LL];                 // w_tc transposed (c, l), PRE-CONVERTED tf32 bits
__device__ float g_wtokT[KTOT * CTD];              // w_tok transposed + padded, PRE-CONVERTED tf32 bits

// -------- helpers --------
__device__ __forceinline__ unsigned f2tf(float x) {
    unsigned u; asm("cvt.rna.tf32.f32 %0, %1;" : "=r"(u) : "f"(x)); return u;
}
__device__ __forceinline__ void mma8(float* c, const unsigned* a, const unsigned* b) {
    asm volatile(
        "mma.sync.aligned.m16n8k8.row.col.f32.tf32.tf32.f32 "
        "{%0,%1,%2,%3},{%4,%5,%6,%7},{%8,%9},{%0,%1,%2,%3};"
        : "+f"(c[0]), "+f"(c[1]), "+f"(c[2]), "+f"(c[3])
        : "r"(a[0]), "r"(a[1]), "r"(a[2]), "r"(a[3]), "r"(b[0]), "r"(b[1]));
}
__device__ __forceinline__ uint32_t smem_u32(const void* p) {
    uint32_t a;
    asm("{ .reg .u64 t; cvta.to.shared.u64 t, %1; cvt.u32.u64 %0, t; }" : "=r"(a) : "l"(p));
    return a;
}
__device__ __forceinline__ void cpa16(uint32_t dst, const void* src) {
    asm volatile("cp.async.cg.shared.global [%0], [%1], 16;" :: "r"(dst), "l"(src));
}
#define CPA_COMMIT() asm volatile("cp.async.commit_group;" ::: "memory")
#define CPA_WAIT3()  asm volatile("cp.async.wait_group 3;" ::: "memory")
#define CPA_WAIT2()  asm volatile("cp.async.wait_group 2;" ::: "memory")
#define CPA_WAIT1()  asm volatile("cp.async.wait_group 1;" ::: "memory")
#define CPA_WAIT0()  asm volatile("cp.async.wait_group 0;" ::: "memory")
#define WAIT_LADDER(rem) do {                              \
    if ((rem) >= 3) CPA_WAIT3();                           \
    else if ((rem) == 2) CPA_WAIT2();                      \
    else if ((rem) == 1) CPA_WAIT1();                      \
    else CPA_WAIT0();                                      \
} while (0)

// -------- tiny weight preprocessing (pre-convert to tf32 bits) --------
__global__ void k_tr_wtc(const float* __restrict__ w_tc) {
    int idx = blockIdx.x * 256 + threadIdx.x;          // 32768
    int c = idx >> 6, l = idx & 63;
    g_wtcT[idx] = __uint_as_float(f2tf(w_tc[l * CCH + c]));
}
__global__ void k_tr_wtok(const float* __restrict__ w_tok) {
    int idx = blockIdx.x * 256 + threadIdx.x;          // 294912
    int k = idx >> 9, d = idx & 511;
    g_wtokT[idx] = (k < 561) ? __uint_as_float(f2tf(w_tok[d * 561 + k])) : 0.0f;
}

#define SA1 136   // K1 A stride, k-major: frag bank 8*tig+gid, conflict-free
#define SMM 20    // K5 A stride, m-major: frag bank 20*gid+tig -> all distinct, conflict-free
#define SBR 72    // B stride: frag bank 8*tig+gid, conflict-free
// k_final repack constants (unchanged)
#define SKM 136
#define PKA_T 72
#define PKB_T 40
#define PKA_SZ 576
#define PKB_SZ 320
#define REPACK_B(rawBbuf) do {                                                        \
    int ksb = rw & 1, qn = rw >> 1;                                                   \
    const float* Rb = (rawBbuf);                                                      \
    int k0 = 8 * ksb + rt, nn0 = 16 * qn + rg;                                        \
    uint4 qb = make_uint4(f2tf(Rb[k0 * SBR + nn0]),  f2tf(Rb[(k0 + 4) * SBR + nn0]),  \
                          f2tf(Rb[k0 * SBR + nn0 + 8]), f2tf(Rb[(k0 + 4) * SBR + nn0 + 8])); \
    pkB[(ksb * 4 + rt) * PKB_T + qn * 8 + rg + 2 * rt] = qb;                          \
} while (0)
#define MMA_PHASE() do {                                                              \
    _Pragma("unroll")                                                                 \
    for (int ks = 0; ks < 2; ++ks) {                                                  \
        uint4 af0 = pkA[(ks * 4 + tig) * PKA_T + (2 * wm + 0) * 8 + gid + 2 * tig];   \
        uint4 af1 = pkA[(ks * 4 + tig) * PKA_T + (2 * wm + 1) * 8 + gid + 2 * tig];   \
        uint4 bf0 = pkB[(ks * 4 + tig) * PKB_T + (2 * wn + 0) * 8 + gid + 2 * tig];   \
        uint4 bf1 = pkB[(ks * 4 + tig) * PKB_T + (2 * wn + 1) * 8 + gid + 2 * tig];   \
        unsigned b0[2] = {bf0.x, bf0.y}, b1[2] = {bf0.z, bf0.w};                      \
        unsigned b2[2] = {bf1.x, bf1.y}, b3[2] = {bf1.z, bf1.w};                      \
        mma8(c[0][0], (const unsigned*)&af0, b0);                                     \
        mma8(c[0][1], (const unsigned*)&af0, b1);                                     \
        mma8(c[0][2], (const unsigned*)&af0, b2);                                     \
        mma8(c[0][3], (const unsigned*)&af0, b3);                                     \
        mma8(c[1][0], (const unsigned*)&af1, b0);                                     \
        mma8(c[1][1], (const unsigned*)&af1, b1);                                     \
        mma8(c[1][2], (const unsigned*)&af1, b2);                                     \
        mma8(c[1][3], (const unsigned*)&af1, b3);                                     \
    }                                                                                 \
} while (0)

// -------- K1: logits + fused per-CTA softmax partials. Tile 128(hw)x64(l), K=512, depth-4 --------
#define K1_AB (16 * SA1)                  // 2176 floats per A buffer
#define K1_BB (16 * SBR)                  // 1152 floats per B buffer
#define K1_DYN ((4 * K1_AB + 4 * K1_BB) * 4)   // 53248 B
__global__ __launch_bounds__(256, 3) void k_logits_mma(const float* __restrict__ feat,
                                                       const float* __restrict__ b_tc) {
    extern __shared__ __align__(16) float dyn[];
    __shared__ float sm_m[4][64], sm_s[4][64];
    int m0 = blockIdx.x * 128, n = blockIdx.y;
    int t = threadIdx.x, wid = t >> 5, lane = t & 31;
    int gid = lane >> 2, tig = lane & 3;
    int wm = wid >> 1, wn = wid & 1;
    const float* fb = feat + (size_t)n * CCH * HWD;
    uint32_t sAb = smem_u32(dyn);
    uint32_t sBb = smem_u32(dyn + 4 * K1_AB);
    float c[2][4][4] = {};

    int ar0 = t >> 5, ac4 = (t & 31) * 4;
    int mg0 = m0 + ac4; if (mg0 > HWD - 4) mg0 = HWD - 4;
    int br = t >> 4, bc4 = (t & 15) * 4;
    int cr = t >> 4, cc8 = (t & 15) * 8;   // A in-place convert mapping (16 rows x 128 cols)

    auto issue = [&](int sl) {
        int b = sl & 3, kk = sl * 16;
        cpa16(sAb + (b * K1_AB + ar0 * SA1 + ac4) * 4, fb + (size_t)(kk + ar0) * HWD + mg0);
        cpa16(sAb + (b * K1_AB + (ar0 + 8) * SA1 + ac4) * 4, fb + (size_t)(kk + ar0 + 8) * HWD + mg0);
        cpa16(sBb + (b * K1_BB + br * SBR + bc4) * 4, g_wtcT + (size_t)(kk + br) * LL + bc4);
        CPA_COMMIT();
    };
    issue(0); issue(1); issue(2);

    for (int s = 0; s < 32; ++s) {
        int rem = 31 - s;
        if (rem >= 3) issue(s + 3);
        WAIT_LADDER(rem);
        __syncthreads();
        float* Ab = dyn + (s & 3) * K1_AB;
        const float* Bb = dyn + 4 * K1_AB + (s & 3) * K1_BB;
        {   // A in-place tf32 convert: each element once (8 per thread)
            float* p = Ab + cr * SA1 + cc8;
            float4 v0 = *(float4*)p, v1 = *(float4*)(p + 4);
            uint4 u0 = {f2tf(v0.x), f2tf(v0.y), f2tf(v0.z), f2tf(v0.w)};
            uint4 u1 = {f2tf(v1.x), f2tf(v1.y), f2tf(v1.z), f2tf(v1.w)};
            *(uint4*)p = u0; *(uint4*)(p + 4) = u1;
        }
        __syncthreads();
#pragma unroll
        for (int ks = 0; ks < 2; ++ks) {
            int kb = ks * 8;
            unsigned a[2][4], b[4][2];
#pragma unroll
            for (int mi = 0; mi < 2; ++mi) {
                int r0 = wm * 32 + mi * 16 + gid;
                a[mi][0] = __float_as_uint(Ab[(kb + tig) * SA1 + r0]);
                a[mi][1] = __float_as_uint(Ab[(kb + tig) * SA1 + r0 + 8]);
                a[mi][2] = __float_as_uint(Ab[(kb + tig + 4) * SA1 + r0]);
                a[mi][3] = __float_as_uint(Ab[(kb + tig + 4) * SA1 + r0 + 8]);
            }
#pragma unroll
            for (int ni = 0; ni < 4; ++ni) {
                int nn = wn * 32 + ni * 8 + gid;
                b[ni][0] = __float_as_uint(Bb[(kb + tig) * SBR + nn]);
                b[ni][1] = __float_as_uint(Bb[(kb + tig + 4) * SBR + nn]);
            }
#pragma unroll
            for (int mi = 0; mi < 2; ++mi)
#pragma unroll
                for (int ni = 0; ni < 4; ++ni) mma8(c[mi][ni], a[mi], b[ni]);
        }
        __syncthreads();
    }
    // ---- epilogue: store raw scaled logits + per-CTA online-softmax partials ----
    const float inv = 0.044194173824159216f;   // 1/sqrt(512)
    float* ob = g_tc + (size_t)n * HWD * LL;
    float bt0[4], bt1[4];
#pragma unroll
    for (int ni = 0; ni < 4; ++ni) {
        int col = wn * 32 + ni * 8 + tig * 2;
        bt0[ni] = b_tc[col]; bt1[ni] = b_tc[col + 1];
    }
    float m8[4][2], s8[4][2];
#pragma unroll
    for (int ni = 0; ni < 4; ++ni) { m8[ni][0] = m8[ni][1] = -1e30f; s8[ni][0] = s8[ni][1] = 0.0f; }
#pragma unroll
    for (int mi = 0; mi < 2; ++mi)
#pragma unroll
        for (int ni = 0; ni < 4; ++ni) {
            int col = wn * 32 + ni * 8 + tig * 2;
#pragma unroll
            for (int h = 0; h < 2; ++h) {
                int hw = m0 + wm * 32 + mi * 16 + gid + h * 8;
                if (hw < HWD) {
                    float v0 = (c[mi][ni][h * 2] + bt0[ni]) * inv;
                    float v1 = (c[mi][ni][h * 2 + 1] + bt1[ni]) * inv;
                    *(float2*)(ob + (size_t)hw * LL + col) = make_float2(v0, v1);
                    m8[ni][0] = fmaxf(m8[ni][0], v0);
                    m8[ni][1] = fmaxf(m8[ni][1], v1);
                }
            }
        }
#pragma unroll
    for (int ni = 0; ni < 4; ++ni)
#pragma unroll
        for (int q = 0; q < 2; ++q) {
            float m = m8[ni][q];
            m = fmaxf(m, __shfl_xor_sync(~0u, m, 4));
            m = fmaxf(m, __shfl_xor_sync(~0u, m, 8));
            m = fmaxf(m, __shfl_xor_sync(~0u, m, 16));
            m8[ni][q] = m;
        }
#pragma unroll
    for (int mi = 0; mi < 2; ++mi)
#pragma unroll
        for (int ni = 0; ni < 4; ++ni)
#pragma unroll
            for (int h = 0; h < 2; ++h) {
                int hw = m0 + wm * 32 + mi * 16 + gid + h * 8;
                if (hw < HWD) {
                    float v0 = (c[mi][ni][h * 2] + bt0[ni]) * inv;
                    float v1 = (c[mi][ni][h * 2 + 1] + bt1[ni]) * inv;
                    s8[ni][0] += __expf(v0 - m8[ni][0]);
                    s8[ni][1] += __expf(v1 - m8[ni][1]);
                }
            }
#pragma unroll
    for (int ni = 0; ni < 4; ++ni)
#pragma unroll
        for (int q = 0; q < 2; ++q) {
            float s = s8[ni][q];
            s += __shfl_xor_sync(~0u, s, 4);
            s += __shfl_xor_sync(~0u, s, 8);
            s += __shfl_xor_sync(~0u, s, 16);
            s8[ni][q] = s;
        }
    if (gid == 0) {
#pragma unroll
        for (int ni = 0; ni < 4; ++ni)
#pragma unroll
            for (int q = 0; q < 2; ++q) {
                int l = wn * 32 + ni * 8 + tig * 2 + q;
                sm_m[wm][l] = m8[ni][q];
                sm_s[wm][l] = s8[ni][q];
            }
    }
    __syncthreads();
    if (t < 64) {
        float M = sm_m[0][t], S = sm_s[0][t];
#pragma unroll
        for (int w = 1; w < 4; ++w) {
            float m2 = sm_m[w][t], s2 = sm_s[w][t];
            float nm = fmaxf(M, m2);
            S = S * __expf(M - nm) + s2 * __expf(m2 - nm);
            M = nm;
        }
        g_part[((n * NCH + blockIdx.x) * 64 + t) * 2 + 0] = M;
        g_part[((n * NCH + blockIdx.x) * 64 + t) * 2 + 1] = S;
    }
}

// -------- K5: A = sum_hw feat * softmax(logits); all converts in transform phase; depth-4 --------
#define K5_AB (128 * SMM)                 // 2560 floats per A buffer
#define K5_BB (16 * SBR)                  // 1152 floats per B buffer
#define K5_DYN ((4 * K5_AB + 4 * K5_BB) * 4)   // 59392 B
__global__ __launch_bounds__(256, 3) void k_agemm(const float* __restrict__ feat) {
    extern __shared__ __align__(16) float dyn[];
    __shared__ float sM[64], sI[64];
    int c0 = blockIdx.x * 128, part = blockIdx.y, n = 31 - blockIdx.z;
    int hwb = part * 784;
    int t = threadIdx.x, wid = t >> 5, lane = t & 31;
    int gid = lane >> 2, tig = lane & 3;
    int wm = wid >> 1, wn = wid & 1;
    const float* fa = feat + ((size_t)n * CCH + c0) * HWD + hwb;
    const float* tb = g_tc + ((size_t)n * HWD + hwb) * LL;
    uint32_t sAb = smem_u32(dyn);
    uint32_t sBb = smem_u32(dyn + 4 * K5_AB);
    float c[2][4][4] = {};

    int am = t >> 1, ak = (t & 1) * 8;
    int br = t >> 4, bc4 = (t & 15) * 4;

    auto issue = [&](int sl) {
        int b = sl & 3, kk = sl * 16;
        cpa16(sAb + (b * K5_AB + am * SMM + ak) * 4, fa + (size_t)am * HWD + kk + ak);
        cpa16(sAb + (b * K5_AB + am * SMM + ak + 4) * 4, fa + (size_t)am * HWD + kk + ak + 4);
        cpa16(sBb + (b * K5_BB + br * SBR + bc4) * 4, tb + (size_t)(kk + br) * LL + bc4);
        CPA_COMMIT();
    };
    issue(0); issue(1); issue(2);

    // folded softmax merge (overlaps first slabs in flight)
    if (t < 64) {
        float M = -1e30f, S = 0.0f;
#pragma unroll
        for (int ch = 0; ch < NCH; ++ch) {
            float m = g_part[((n * NCH + ch) * 64 + t) * 2 + 0];
            float s = g_part[((n * NCH + ch) * 64 + t) * 2 + 1];
            float nm = fmaxf(M, m);
            S = S * __expf(M - nm) + s * __expf(m - nm);
            M = nm;
        }
        sM[t] = M;
        sI[t] = 1.0f / S;
    }

    for (int s = 0; s < 49; ++s) {
        int rem = 48 - s;
        if (rem >= 3) issue(s + 3);
        WAIT_LADDER(rem);
        __syncthreads();
        float* Ab = dyn + (s & 3) * K5_AB;
        float* Bb = dyn + 4 * K5_AB + (s & 3) * K5_BB;
        {   // transform phase: B exp+convert (4/thread), A convert (8/thread) — each element once
#pragma unroll
            for (int j = 0; j < 4; ++j) {
                int l = bc4 + j;
                Bb[br * SBR + l] = __uint_as_float(f2tf(__expf(Bb[br * SBR + l] - sM[l]) * sI[l]));
            }
            float* p = Ab + am * SMM + ak;
            float4 v0 = *(float4*)p, v1 = *(float4*)(p + 4);
            uint4 u0 = {f2tf(v0.x), f2tf(v0.y), f2tf(v0.z), f2tf(v0.w)};
            uint4 u1 = {f2tf(v1.x), f2tf(v1.y), f2tf(v1.z), f2tf(v1.w)};
            *(uint4*)p = u0; *(uint4*)(p + 4) = u1;
        }
        __syncthreads();
#pragma unroll
        for (int ks = 0; ks < 2; ++ks) {
            int kb = ks * 8;
            unsigned a[2][4], b[4][2];
#pragma unroll
            for (int mi = 0; mi < 2; ++mi) {
                int r0 = wm * 32 + mi * 16 + gid;
                a[mi][0] = __float_as_uint(Ab[r0 * SMM + kb + tig]);
                a[mi][1] = __float_as_uint(Ab[(r0 + 8) * SMM + kb + tig]);
                a[mi][2] = __float_as_uint(Ab[r0 * SMM + kb + tig + 4]);
                a[mi][3] = __float_as_uint(Ab[(r0 + 8) * SMM + kb + tig + 4]);
            }
#pragma unroll
            for (int ni = 0; ni < 4; ++ni) {
                int nn = wn * 32 + ni * 8 + gid;
                b[ni][0] = __float_as_uint(Bb[(kb + tig) * SBR + nn]);
                b[ni][1] = __float_as_uint(Bb[(kb + tig + 4) * SBR + nn]);
            }
#pragma unroll
            for (int mi = 0; mi < 2; ++mi)
#pragma unroll
                for (int ni = 0; ni < 4; ++ni) mma8(c[mi][ni], a[mi], b[ni]);
        }
        __syncthreads();
    }
    float* ob = g_Ap[part] + ((size_t)n * CTD + c0) * LL;
#pragma unroll
    for (int mi = 0; mi < 2; ++mi)
#pragma unroll
        for (int ni = 0; ni < 4; ++ni) {
            int col = wn * 32 + ni * 8 + tig * 2;
#pragma unroll
            for (int h = 0; h < 2; ++h) {
                int row = wm * 32 + mi * 16 + gid + h * 8;
                float2 v = {c[mi][ni][h * 2], c[mi][ni][h * 2 + 1]};
                *(float2*)(ob + (size_t)row * LL + col) = v;
            }
        }
}

// -------- K6: pos-encoder; computes its own (n,l) softmax merge from g_part --------
__global__ void k_pos(const float* __restrict__ w_ds3, const float* __restrict__ b_ds3,
                      const float* __restrict__ w_ds1, const float* __restrict__ b_ds1) {
    int nl = blockIdx.x;                         // n*64 + l
    int n = nl >> 6, l = nl & 63;
    __shared__ float S[196];
    __shared__ float sMI[2];
    int t = threadIdx.x, lane = t & 31;
    if (t < 32) {
        float m = -1e30f, s = 0.0f;
        if (lane < NCH) {
            m = g_part[((n * NCH + lane) * 64 + l) * 2 + 0];
            s = g_part[((n * NCH + lane) * 64 + l) * 2 + 1];
        }
        float M = m;
#pragma unroll
        for (int o = 16; o; o >>= 1) M = fmaxf(M, __shfl_xor_sync(~0u, M, o));
        s *= __expf(m - M);
#pragma unroll
        for (int o = 16; o; o >>= 1) s += __shfl_xor_sync(~0u, s, o);
        if (lane == 0) { sMI[0] = M; sMI[1] = 1.0f / s; }
    }
    __syncthreads();
    float M = sMI[0], I = sMI[1];
    const float* base = g_tc + (size_t)n * HWD * LL + (size_t)l * HWD;  // flat view slice
    for (int q = t; q < 196; q += 64) {
        int i = q / 14, j = q % 14;
        S[q] = __expf(base[i * 224 + j * 4] - M) * I;
    }
    __syncthreads();
    if (t < 49) {
        int oy = t / 7, ox = t % 7;
        float acc = 0.0f;
#pragma unroll
        for (int ky = 0; ky < 3; ++ky)
#pragma unroll
            for (int kx = 0; kx < 3; ++kx) {
                int iy = 2 * oy + ky - 1, ix = 2 * ox + kx - 1;
                if (iy >= 0 && iy < 14 && ix >= 0 && ix < 14)
                    acc += S[iy * 14 + ix] * w_ds3[ky * 3 + kx];
            }
        float v = (acc + b_ds3[0]) * w_ds1[0] + b_ds1[0];
        g_pcp[(size_t)nl * 49 + t] = v;
    }
}

// -------- K7a: grouped mix (sums split-K parts) -> B rows [0,512) --------
__global__ __launch_bounds__(256) void k_mix(const float* __restrict__ w_val,
                                             const float* __restrict__ b_val) {
    int g = blockIdx.x, n = blockIdx.y;
    __shared__ float sA[32][64];
    __shared__ float sW[32][33];
    int t = threadIdx.x;
    size_t abase = ((size_t)n * CTD + g * 32) * LL;
    for (int q = t; q < 2048; q += 256) {
        float v = g_Ap[0][abase + q] + g_Ap[1][abase + q] +
                  g_Ap[2][abase + q] + g_Ap[3][abase + q];
        sA[q >> 6][q & 63] = v;
    }
    for (int q = t; q < 1024; q += 256) sW[q >> 5][q & 31] = w_val[g * 1024 + q];
    __syncthreads();
    for (int q = t; q < 2048; q += 256) {
        int d = q >> 6, l = q & 63;
        float acc = b_val[g * 32 + d];          // sum_hw tc == 1 exactly
#pragma unroll
        for (int c = 0; c < 32; ++c) acc += sW[d][c] * sA[c][l];
        g_B[((size_t)n * KTOT + g * 32 + d) * LL + l] = acc;
    }
}

// -------- K7b: pos rows -> B rows [512,576) (>=561 zero) --------
__global__ __launch_bounds__(256) void k_posrows(const float* __restrict__ w_pos,
                                                 const float* __restrict__ b_pos) {
    int n = blockIdx.x;
    __shared__ float sp[3136];    // (l,49)
    __shared__ float swp[2401];
    int t = threadIdx.x;
    for (int q = t; q < 3136; q += 256) sp[q] = g_pcp[(size_t)n * 3136 + q];
    for (int q = t; q < 2401; q += 256) swp[q] = w_pos[q];
    __syncthreads();
    for (int q = t; q < 4096; q += 256) {
        int p = q >> 6, l = q & 63;
        float v = 0.0f;
        if (p < 49) {
            v = b_pos[p];
            for (int c = 0; c < 49; ++c) v += swp[p * 49 + c] * sp[l * 49 + c];
        }
        g_B[((size_t)n * KTOT + 512 + p) * LL + l] = v;
    }
}

// -------- K8 (tf32 MMA): out[n,d,l] = wtokT^T @ B + b_tok. Tile 128(d)x64(l), K=576 --------
__global__ __launch_bounds__(256) void k_final_mma(const float* __restrict__ b_tok,
                                                   float* __restrict__ out) {
    __shared__ __align__(16) float rawA[2][16 * SKM];
    __shared__ __align__(16) float rawB[2][16 * SBR];
    __shared__ uint4 pkA[PKA_SZ];
    __shared__ uint4 pkB[PKB_SZ];
    int d0 = blockIdx.x * 128, n = blockIdx.y;
    int t = threadIdx.x, wid = t >> 5, lane = t & 31;
    int gid = lane >> 2, tig = lane & 3;
    int wm = wid >> 1, wn = wid & 1;
    int rw = t >> 5, rt = lane >> 3, rg = lane & 7;
    const float* bb = g_B + (size_t)n * KTOT * LL;
    uint32_t sA[2] = {smem_u32(&rawA[0][0]), smem_u32(&rawA[1][0])};
    uint32_t sBm[2] = {smem_u32(&rawB[0][0]), smem_u32(&rawB[1][0])};
    float c[2][4][4] = {};

    int ar0 = t >> 5, ac4 = (t & 31) * 4;
    int br = t >> 4, bc4 = (t & 15) * 4;

    cpa16(sA[0] + (ar0 * SKM + ac4) * 4, g_wtokT + (size_t)ar0 * CTD + d0 + ac4);
    cpa16(sA[0] + ((ar0 + 8) * SKM + ac4) * 4, g_wtokT + (size_t)(ar0 + 8) * CTD + d0 + ac4);
    cpa16(sBm[0] + (br * SBR + bc4) * 4, bb + (size_t)br * LL + bc4);
    CPA_COMMIT();

    for (int s = 0; s < 36; ++s) {
        int buf = s & 1;
        if (s < 35) {
            int k1 = (s + 1) * 16, b1 = (s + 1) & 1;
            cpa16(sA[b1] + (ar0 * SKM + ac4) * 4, g_wtokT + (size_t)(k1 + ar0) * CTD + d0 + ac4);
            cpa16(sA[b1] + ((ar0 + 8) * SKM + ac4) * 4, g_wtokT + (size_t)(k1 + ar0 + 8) * CTD + d0 + ac4);
            cpa16(sBm[b1] + (br * SBR + bc4) * 4, bb + (size_t)(k1 + br) * LL + bc4);
            CPA_COMMIT();
            CPA_WAIT1();
        } else {
            CPA_WAIT0();
        }
        __syncthreads();
#pragma unroll
        for (int ks = 0; ks < 2; ++ks) {
            const float* Ra = rawA[buf];
            int kq = 8 * ks + rt, m = 16 * rw + rg;
            uint4 qa = make_uint4(__float_as_uint(Ra[kq * SKM + m]), __float_as_uint(Ra[kq * SKM + m + 8]),
                                  __float_as_uint(Ra[(kq + 4) * SKM + m]), __float_as_uint(Ra[(kq + 4) * SKM + m + 8]));
            pkA[(ks * 4 + rt) * PKA_T + rw * 8 + rg + 2 * rt] = qa;
        }
        REPACK_B(rawB[buf]);
        __syncthreads();
        MMA_PHASE();
    }
#pragma unroll
    for (int mi = 0; mi < 2; ++mi)
#pragma unroll
        for (int ni = 0; ni < 4; ++ni) {
            int col = wn * 32 + ni * 8 + tig * 2;
#pragma unroll
            for (int h = 0; h < 2; ++h) {
                int d = d0 + wm * 32 + mi * 16 + gid + h * 8;
                float bt = b_tok[d];
                float2 v = {c[mi][ni][h * 2] + bt, c[mi][ni][h * 2 + 1] + bt};
                *(float2*)(out + ((size_t)n * CTD + d) * LL + col) = v;
            }
        }
}

extern "C" void kernel_launch(void* const* d_in, const int* in_sizes, int n_in,
                              void* d_out, int out_size) {
    const float* feat  = (const float*)d_in[0];
    const float* w_tc  = (const float*)d_in[1];
    const float* b_tc  = (const float*)d_in[2];
    const float* w_val = (const float*)d_in[3];
    const float* b_val = (const float*)d_in[4];
    const float* w_ds3 = (const float*)d_in[5];
    const float* b_ds3 = (const float*)d_in[6];
    const float* w_ds1 = (const float*)d_in[7];
    const float* b_ds1 = (const float*)d_in[8];
    const float* w_pos = (const float*)d_in[9];
    const float* b_pos = (const float*)d_in[10];
    const float* w_tok = (const float*)d_in[11];
    const float* b_tok = (const float*)d_in[12];
    float* out = (float*)d_out;

    cudaFuncSetAttribute(k_logits_mma, cudaFuncAttributeMaxDynamicSharedMemorySize, K1_DYN);
    cudaFuncSetAttribute(k_agemm, cudaFuncAttributeMaxDynamicSharedMemorySize, K5_DYN);

    k_tr_wtc<<<128, 256>>>(w_tc);
    k_tr_wtok<<<1152, 256>>>(w_tok);
    k_logits_mma<<<dim3(NCH, 32), 256, K1_DYN>>>(feat, b_tc);
    k_agemm<<<dim3(4, 4, 32), 256, K5_DYN>>>(feat);
    k_pos<<<2048, 64>>>(w_ds3, b_ds3, w_ds1, b_ds1);
    k_mix<<<dim3(16, 32), 256>>>(w_val, b_val);
    k_posrows<<<32, 256>>>(w_pos, b_pos);
    k_final_mma<<<dim3(4, 32), 256>>>(b_tok, out);
}

// round 16
// speedup vs baseline: 1.2448x; 1.2448x over previous
#include <cuda_runtime.h>
#include <cstdint>

#define NB   32
#define CCH  512
#define HWD  3136
#define LL   64
#define CTD  512
#define KTOT 576   // 561 padded to 576
#define NCH  25    // softmax chunks = ceil(3136/128)

// -------- scratch (device globals; no runtime allocation) --------
__device__ float g_tc[(size_t)NB * HWD * LL];      // RAW scaled logits, layout (n, hw, l)
__device__ float g_part[NB * NCH * LL * 2];        // per-CTA online-softmax (m, s)
__device__ float g_Ap[4][(size_t)NB * CTD * LL];   // split-K partials of A (n, c, l)
__device__ float g_pcp[NB * LL * 49];              // pos-encoder conv output (n, l, 49)
__device__ float g_B[(size_t)NB * KTOT * LL];      // concat [tokens0; pos; zeros] (n, 576, l)
__device__ float g_wtcT[CCH * LL];                 // w_tc transposed (c, l), PRE-CONVERTED tf32 bits
__device__ float g_wtokT[KTOT * CTD];              // w_tok transposed + padded, PRE-CONVERTED tf32 bits

// -------- helpers --------
__device__ __forceinline__ unsigned f2tf(float x) {
    unsigned u; asm("cvt.rna.tf32.f32 %0, %1;" : "=r"(u) : "f"(x)); return u;
}
__device__ __forceinline__ void mma8(float* c, const unsigned* a, const unsigned* b) {
    asm volatile(
        "mma.sync.aligned.m16n8k8.row.col.f32.tf32.tf32.f32 "
        "{%0,%1,%2,%3},{%4,%5,%6,%7},{%8,%9},{%0,%1,%2,%3};"
        : "+f"(c[0]), "+f"(c[1]), "+f"(c[2]), "+f"(c[3])
        : "r"(a[0]), "r"(a[1]), "r"(a[2]), "r"(a[3]), "r"(b[0]), "r"(b[1]));
}
__device__ __forceinline__ uint32_t smem_u32(const void* p) {
    uint32_t a;
    asm("{ .reg .u64 t; cvta.to.shared.u64 t, %1; cvt.u32.u64 %0, t; }" : "=r"(a) : "l"(p));
    return a;
}
__device__ __forceinline__ void cpa16(uint32_t dst, const void* src) {
    asm volatile("cp.async.cg.shared.global [%0], [%1], 16;" :: "r"(dst), "l"(src));
}
#define CPA_COMMIT() asm volatile("cp.async.commit_group;" ::: "memory")
#define CPA_WAIT3()  asm volatile("cp.async.wait_group 3;" ::: "memory")
#define CPA_WAIT2()  asm volatile("cp.async.wait_group 2;" ::: "memory")
#define CPA_WAIT1()  asm volatile("cp.async.wait_group 1;" ::: "memory")
#define CPA_WAIT0()  asm volatile("cp.async.wait_group 0;" ::: "memory")
#define WAIT_LADDER(rem) do {                              \
    if ((rem) >= 3) CPA_WAIT3();                           \
    else if ((rem) == 2) CPA_WAIT2();                      \
    else if ((rem) == 1) CPA_WAIT1();                      \
    else CPA_WAIT0();                                      \
} while (0)

// -------- tiny weight preprocessing (pre-convert to tf32 bits; off hot path) --------
__global__ void k_tr_wtc(const float* __restrict__ w_tc) {
    int idx = blockIdx.x * 256 + threadIdx.x;          // 32768
    int c = idx >> 6, l = idx & 63;
    g_wtcT[idx] = __uint_as_float(f2tf(w_tc[l * CCH + c]));
}
__global__ void k_tr_wtok(const float* __restrict__ w_tok) {
    int idx = blockIdx.x * 256 + threadIdx.x;          // 294912
    int k = idx >> 9, d = idx & 511;
    g_wtokT[idx] = (k < 561) ? __uint_as_float(f2tf(w_tok[d * 561 + k])) : 0.0f;
}

#define SA1 136   // K1 A stride, k-major: frag bank 8*tig+gid, conflict-free
#define SMM 20    // K5 A stride, m-major: frag bank 20*gid+tig -> all distinct, conflict-free
#define SBR 72    // B stride: frag bank 8*tig+gid, conflict-free
// k_final repack constants
#define SKM 136
#define PKA_T 72
#define PKB_T 40
#define PKA_SZ 576
#define PKB_SZ 320
#define REPACK_B(rawBbuf) do {                                                        \
    int ksb = rw & 1, qn = rw >> 1;                                                   \
    const float* Rb = (rawBbuf);                                                      \
    int k0 = 8 * ksb + rt, nn0 = 16 * qn + rg;                                        \
    uint4 qb = make_uint4(f2tf(Rb[k0 * SBR + nn0]),  f2tf(Rb[(k0 + 4) * SBR + nn0]),  \
                          f2tf(Rb[k0 * SBR + nn0 + 8]), f2tf(Rb[(k0 + 4) * SBR + nn0 + 8])); \
    pkB[(ksb * 4 + rt) * PKB_T + qn * 8 + rg + 2 * rt] = qb;                          \
} while (0)
#define MMA_PHASE() do {                                                              \
    _Pragma("unroll")                                                                 \
    for (int ks = 0; ks < 2; ++ks) {                                                  \
        uint4 af0 = pkA[(ks * 4 + tig) * PKA_T + (2 * wm + 0) * 8 + gid + 2 * tig];   \
        uint4 af1 = pkA[(ks * 4 + tig) * PKA_T + (2 * wm + 1) * 8 + gid + 2 * tig];   \
        uint4 bf0 = pkB[(ks * 4 + tig) * PKB_T + (2 * wn + 0) * 8 + gid + 2 * tig];   \
        uint4 bf1 = pkB[(ks * 4 + tig) * PKB_T + (2 * wn + 1) * 8 + gid + 2 * tig];   \
        unsigned b0[2] = {bf0.x, bf0.y}, b1[2] = {bf0.z, bf0.w};                      \
        unsigned b2[2] = {bf1.x, bf1.y}, b3[2] = {bf1.z, bf1.w};                      \
        mma8(c[0][0], (const unsigned*)&af0, b0);                                     \
        mma8(c[0][1], (const unsigned*)&af0, b1);                                     \
        mma8(c[0][2], (const unsigned*)&af0, b2);                                     \
        mma8(c[0][3], (const unsigned*)&af0, b3);                                     \
        mma8(c[1][0], (const unsigned*)&af1, b0);                                     \
        mma8(c[1][1], (const unsigned*)&af1, b1);                                     \
        mma8(c[1][2], (const unsigned*)&af1, b2);                                     \
        mma8(c[1][3], (const unsigned*)&af1, b3);                                     \
    }                                                                                 \
} while (0)

// -------- K1: logits + fused per-CTA softmax partials. Tile 128(hw)x64(l), K=512, depth-4 --------
#define K1_AB (16 * SA1)                  // 2176 floats per A buffer
#define K1_BB (16 * SBR)                  // 1152 floats per B buffer
#define K1_DYN ((4 * K1_AB + 4 * K1_BB) * 4)   // 53248 B
__global__ __launch_bounds__(256, 3) void k_logits_mma(const float* __restrict__ feat,
                                                       const float* __restrict__ b_tc) {
    extern __shared__ __align__(16) float dyn[];
    __shared__ float sm_m[4][64], sm_s[4][64];
    int m0 = blockIdx.x * 128, n = blockIdx.y;
    int t = threadIdx.x, wid = t >> 5, lane = t & 31;
    int gid = lane >> 2, tig = lane & 3;
    int wm = wid >> 1, wn = wid & 1;
    const float* fb = feat + (size_t)n * CCH * HWD;
    uint32_t sAb = smem_u32(dyn);
    uint32_t sBb = smem_u32(dyn + 4 * K1_AB);
    float c[2][4][4] = {};

    int ar0 = t >> 5, ac4 = (t & 31) * 4;
    int mg0 = m0 + ac4; if (mg0 > HWD - 4) mg0 = HWD - 4;
    int br = t >> 4, bc4 = (t & 15) * 4;

    auto issue = [&](int sl) {
        int b = sl & 3, kk = sl * 16;
        cpa16(sAb + (b * K1_AB + ar0 * SA1 + ac4) * 4, fb + (size_t)(kk + ar0) * HWD + mg0);
        cpa16(sAb + (b * K1_AB + (ar0 + 8) * SA1 + ac4) * 4, fb + (size_t)(kk + ar0 + 8) * HWD + mg0);
        cpa16(sBb + (b * K1_BB + br * SBR + bc4) * 4, g_wtcT + (size_t)(kk + br) * LL + bc4);
        CPA_COMMIT();
    };
    issue(0); issue(1); issue(2);

    for (int s = 0; s < 32; ++s) {
        int rem = 31 - s;
        if (rem >= 3) issue(s + 3);
        WAIT_LADDER(rem);
        __syncthreads();
        const float* Ab = dyn + (s & 3) * K1_AB;
        const float* Bb = dyn + 4 * K1_AB + (s & 3) * K1_BB;
#pragma unroll
        for (int ks = 0; ks < 2; ++ks) {
            int kb = ks * 8;
            unsigned a[2][4], b[4][2];
#pragma unroll
            for (int mi = 0; mi < 2; ++mi) {
                int r0 = wm * 32 + mi * 16 + gid;
                a[mi][0] = f2tf(Ab[(kb + tig) * SA1 + r0]);
                a[mi][1] = f2tf(Ab[(kb + tig) * SA1 + r0 + 8]);
                a[mi][2] = f2tf(Ab[(kb + tig + 4) * SA1 + r0]);
                a[mi][3] = f2tf(Ab[(kb + tig + 4) * SA1 + r0 + 8]);
            }
#pragma unroll
            for (int ni = 0; ni < 4; ++ni) {
                int nn = wn * 32 + ni * 8 + gid;
                b[ni][0] = __float_as_uint(Bb[(kb + tig) * SBR + nn]);       // pre-converted
                b[ni][1] = __float_as_uint(Bb[(kb + tig + 4) * SBR + nn]);
            }
#pragma unroll
            for (int mi = 0; mi < 2; ++mi)
#pragma unroll
                for (int ni = 0; ni < 4; ++ni) mma8(c[mi][ni], a[mi], b[ni]);
        }
        __syncthreads();
    }
    // ---- epilogue: store raw scaled logits + per-CTA online-softmax partials ----
    const float inv = 0.044194173824159216f;   // 1/sqrt(512)
    float* ob = g_tc + (size_t)n * HWD * LL;
    float bt0[4], bt1[4];
#pragma unroll
    for (int ni = 0; ni < 4; ++ni) {
        int col = wn * 32 + ni * 8 + tig * 2;
        bt0[ni] = b_tc[col]; bt1[ni] = b_tc[col + 1];
    }
    float m8[4][2], s8[4][2];
#pragma unroll
    for (int ni = 0; ni < 4; ++ni) { m8[ni][0] = m8[ni][1] = -1e30f; s8[ni][0] = s8[ni][1] = 0.0f; }
#pragma unroll
    for (int mi = 0; mi < 2; ++mi)
#pragma unroll
        for (int ni = 0; ni < 4; ++ni) {
            int col = wn * 32 + ni * 8 + tig * 2;
#pragma unroll
            for (int h = 0; h < 2; ++h) {
                int hw = m0 + wm * 32 + mi * 16 + gid + h * 8;
                if (hw < HWD) {
                    float v0 = (c[mi][ni][h * 2] + bt0[ni]) * inv;
                    float v1 = (c[mi][ni][h * 2 + 1] + bt1[ni]) * inv;
                    *(float2*)(ob + (size_t)hw * LL + col) = make_float2(v0, v1);
                    m8[ni][0] = fmaxf(m8[ni][0], v0);
                    m8[ni][1] = fmaxf(m8[ni][1], v1);
                }
            }
        }
#pragma unroll
    for (int ni = 0; ni < 4; ++ni)
#pragma unroll
        for (int q = 0; q < 2; ++q) {
            float m = m8[ni][q];
            m = fmaxf(m, __shfl_xor_sync(~0u, m, 4));
            m = fmaxf(m, __shfl_xor_sync(~0u, m, 8));
            m = fmaxf(m, __shfl_xor_sync(~0u, m, 16));
            m8[ni][q] = m;
        }
#pragma unroll
    for (int mi = 0; mi < 2; ++mi)
#pragma unroll
        for (int ni = 0; ni < 4; ++ni)
#pragma unroll
            for (int h = 0; h < 2; ++h) {
                int hw = m0 + wm * 32 + mi * 16 + gid + h * 8;
                if (hw < HWD) {
                    float v0 = (c[mi][ni][h * 2] + bt0[ni]) * inv;
                    float v1 = (c[mi][ni][h * 2 + 1] + bt1[ni]) * inv;
                    s8[ni][0] += __expf(v0 - m8[ni][0]);
                    s8[ni][1] += __expf(v1 - m8[ni][1]);
                }
            }
#pragma unroll
    for (int ni = 0; ni < 4; ++ni)
#pragma unroll
        for (int q = 0; q < 2; ++q) {
            float s = s8[ni][q];
            s += __shfl_xor_sync(~0u, s, 4);
            s += __shfl_xor_sync(~0u, s, 8);
            s += __shfl_xor_sync(~0u, s, 16);
            s8[ni][q] = s;
        }
    if (gid == 0) {
#pragma unroll
        for (int ni = 0; ni < 4; ++ni)
#pragma unroll
            for (int q = 0; q < 2; ++q) {
                int l = wn * 32 + ni * 8 + tig * 2 + q;
                sm_m[wm][l] = m8[ni][q];
                sm_s[wm][l] = s8[ni][q];
            }
    }
    __syncthreads();
    if (t < 64) {
        float M = sm_m[0][t], S = sm_s[0][t];
#pragma unroll
        for (int w = 1; w < 4; ++w) {
            float m2 = sm_m[w][t], s2 = sm_s[w][t];
            float nm = fmaxf(M, m2);
            S = S * __expf(M - nm) + s2 * __expf(m2 - nm);
            M = nm;
        }
        g_part[((n * NCH + blockIdx.x) * 64 + t) * 2 + 0] = M;
        g_part[((n * NCH + blockIdx.x) * 64 + t) * 2 + 1] = S;
    }
}

// -------- K5: A = sum_hw feat * softmax(logits); B exp+cvt transform (1x/elem); depth-4 --------
#define K5_AB (128 * SMM)                 // 2560 floats per A buffer
#define K5_BB (16 * SBR)                  // 1152 floats per B buffer
#define K5_DYN ((4 * K5_AB + 4 * K5_BB) * 4)   // 59392 B
__global__ __launch_bounds__(256, 3) void k_agemm(const float* __restrict__ feat) {
    extern __shared__ __align__(16) float dyn[];
    __shared__ float sM[64], sI[64];
    int c0 = blockIdx.x * 128, part = blockIdx.y, n = 31 - blockIdx.z;
    int hwb = part * 784;
    int t = threadIdx.x, wid = t >> 5, lane = t & 31;
    int gid = lane >> 2, tig = lane & 3;
    int wm = wid >> 1, wn = wid & 1;
    const float* fa = feat + ((size_t)n * CCH + c0) * HWD + hwb;
    const float* tb = g_tc + ((size_t)n * HWD + hwb) * LL;
    uint32_t sAb = smem_u32(dyn);
    uint32_t sBb = smem_u32(dyn + 4 * K5_AB);
    float c[2][4][4] = {};

    int am = t >> 1, ak = (t & 1) * 8;
    int br = t >> 4, bc4 = (t & 15) * 4;

    auto issue = [&](int sl) {
        int b = sl & 3, kk = sl * 16;
        cpa16(sAb + (b * K5_AB + am * SMM + ak) * 4, fa + (size_t)am * HWD + kk + ak);
        cpa16(sAb + (b * K5_AB + am * SMM + ak + 4) * 4, fa + (size_t)am * HWD + kk + ak + 4);
        cpa16(sBb + (b * K5_BB + br * SBR + bc4) * 4, tb + (size_t)(kk + br) * LL + bc4);
        CPA_COMMIT();
    };
    issue(0); issue(1); issue(2);

    // folded softmax merge (overlaps first slabs in flight)
    if (t < 64) {
        float M = -1e30f, S = 0.0f;
#pragma unroll
        for (int ch = 0; ch < NCH; ++ch) {
            float m = g_part[((n * NCH + ch) * 64 + t) * 2 + 0];
            float s = g_part[((n * NCH + ch) * 64 + t) * 2 + 1];
            float nm = fmaxf(M, m);
            S = S * __expf(M - nm) + s * __expf(m - nm);
            M = nm;
        }
        sM[t] = M;
        sI[t] = 1.0f / S;
    }

    for (int s = 0; s < 49; ++s) {
        int rem = 48 - s;
        if (rem >= 3) issue(s + 3);
        WAIT_LADDER(rem);
        __syncthreads();
        const float* Ab = dyn + (s & 3) * K5_AB;
        float* Bb = dyn + 4 * K5_AB + (s & 3) * K5_BB;
        {   // B transform: exp + tf32 convert, each element once (4 per thread)
#pragma unroll
            for (int j = 0; j < 4; ++j) {
                int l = bc4 + j;
                Bb[br * SBR + l] = __uint_as_float(f2tf(__expf(Bb[br * SBR + l] - sM[l]) * sI[l]));
            }
        }
        __syncthreads();
#pragma unroll
        for (int ks = 0; ks < 2; ++ks) {
            int kb = ks * 8;
            unsigned a[2][4], b[4][2];
#pragma unroll
            for (int mi = 0; mi < 2; ++mi) {
                int r0 = wm * 32 + mi * 16 + gid;
                a[mi][0] = f2tf(Ab[r0 * SMM + kb + tig]);
                a[mi][1] = f2tf(Ab[(r0 + 8) * SMM + kb + tig]);
                a[mi][2] = f2tf(Ab[r0 * SMM + kb + tig + 4]);
                a[mi][3] = f2tf(Ab[(r0 + 8) * SMM + kb + tig + 4]);
            }
#pragma unroll
            for (int ni = 0; ni < 4; ++ni) {
                int nn = wn * 32 + ni * 8 + gid;
                b[ni][0] = __float_as_uint(Bb[(kb + tig) * SBR + nn]);       // pre-converted
                b[ni][1] = __float_as_uint(Bb[(kb + tig + 4) * SBR + nn]);
            }
#pragma unroll
            for (int mi = 0; mi < 2; ++mi)
#pragma unroll
                for (int ni = 0; ni < 4; ++ni) mma8(c[mi][ni], a[mi], b[ni]);
        }
        __syncthreads();
    }
    float* ob = g_Ap[part] + ((size_t)n * CTD + c0) * LL;
#pragma unroll
    for (int mi = 0; mi < 2; ++mi)
#pragma unroll
        for (int ni = 0; ni < 4; ++ni) {
            int col = wn * 32 + ni * 8 + tig * 2;
#pragma unroll
            for (int h = 0; h < 2; ++h) {
                int row = wm * 32 + mi * 16 + gid + h * 8;
                float2 v = {c[mi][ni][h * 2], c[mi][ni][h * 2 + 1]};
                *(float2*)(ob + (size_t)row * LL + col) = v;
            }
        }
}

// -------- K6: pos-encoder; computes its own (n,l) softmax merge from g_part --------
__global__ void k_pos(const float* __restrict__ w_ds3, const float* __restrict__ b_ds3,
                      const float* __restrict__ w_ds1, const float* __restrict__ b_ds1) {
    int nl = blockIdx.x;                         // n*64 + l
    int n = nl >> 6, l = nl & 63;
    __shared__ float S[196];
    __shared__ float sMI[2];
    int t = threadIdx.x, lane = t & 31;
    if (t < 32) {
        float m = -1e30f, s = 0.0f;
        if (lane < NCH) {
            m = g_part[((n * NCH + lane) * 64 + l) * 2 + 0];
            s = g_part[((n * NCH + lane) * 64 + l) * 2 + 1];
        }
        float M = m;
#pragma unroll
        for (int o = 16; o; o >>= 1) M = fmaxf(M, __shfl_xor_sync(~0u, M, o));
        s *= __expf(m - M);
#pragma unroll
        for (int o = 16; o; o >>= 1) s += __shfl_xor_sync(~0u, s, o);
        if (lane == 0) { sMI[0] = M; sMI[1] = 1.0f / s; }
    }
    __syncthreads();
    float M = sMI[0], I = sMI[1];
    const float* base = g_tc + (size_t)n * HWD * LL + (size_t)l * HWD;  // flat view slice
    for (int q = t; q < 196; q += 64) {
        int i = q / 14, j = q % 14;
        S[q] = __expf(base[i * 224 + j * 4] - M) * I;
    }
    __syncthreads();
    if (t < 49) {
        int oy = t / 7, ox = t % 7;
        float acc = 0.0f;
#pragma unroll
        for (int ky = 0; ky < 3; ++ky)
#pragma unroll
            for (int kx = 0; kx < 3; ++kx) {
                int iy = 2 * oy + ky - 1, ix = 2 * ox + kx - 1;
                if (iy >= 0 && iy < 14 && ix >= 0 && ix < 14)
                    acc += S[iy * 14 + ix] * w_ds3[ky * 3 + kx];
            }
        float v = (acc + b_ds3[0]) * w_ds1[0] + b_ds1[0];
        g_pcp[(size_t)nl * 49 + t] = v;
    }
}

// -------- K7a: grouped mix (sums split-K parts) -> B rows [0,512) --------
__global__ __launch_bounds__(256) void k_mix(const float* __restrict__ w_val,
                                             const float* __restrict__ b_val) {
    int g = blockIdx.x, n = blockIdx.y;
    __shared__ float sA[32][64];
    __shared__ float sW[32][33];
    int t = threadIdx.x;
    size_t abase = ((size_t)n * CTD + g * 32) * LL;
    for (int q = t; q < 2048; q += 256) {
        float v = g_Ap[0][abase + q] + g_Ap[1][abase + q] +
                  g_Ap[2][abase + q] + g_Ap[3][abase + q];
        sA[q >> 6][q & 63] = v;
    }
    for (int q = t; q < 1024; q += 256) sW[q >> 5][q & 31] = w_val[g * 1024 + q];
    __syncthreads();
    for (int q = t; q < 2048; q += 256) {
        int d = q >> 6, l = q & 63;
        float acc = b_val[g * 32 + d];          // sum_hw tc == 1 exactly
#pragma unroll
        for (int c = 0; c < 32; ++c) acc += sW[d][c] * sA[c][l];
        g_B[((size_t)n * KTOT + g * 32 + d) * LL + l] = acc;
    }
}

// -------- K7b: pos rows -> B rows [512,576) (>=561 zero) --------
__global__ __launch_bounds__(256) void k_posrows(const float* __restrict__ w_pos,
                                                 const float* __restrict__ b_pos) {
    int n = blockIdx.x;
    __shared__ float sp[3136];    // (l,49)
    __shared__ float swp[2401];
    int t = threadIdx.x;
    for (int q = t; q < 3136; q += 256) sp[q] = g_pcp[(size_t)n * 3136 + q];
    for (int q = t; q < 2401; q += 256) swp[q] = w_pos[q];
    __syncthreads();
    for (int q = t; q < 4096; q += 256) {
        int p = q >> 6, l = q & 63;
        float v = 0.0f;
        if (p < 49) {
            v = b_pos[p];
            for (int c = 0; c < 49; ++c) v += swp[p * 49 + c] * sp[l * 49 + c];
        }
        g_B[((size_t)n * KTOT + 512 + p) * LL + l] = v;
    }
}

// -------- K8 (tf32 MMA): out[n,d,l] = wtokT^T @ B + b_tok. Tile 128(d)x64(l), K=576 --------
__global__ __launch_bounds__(256) void k_final_mma(const float* __restrict__ b_tok,
                                                   float* __restrict__ out) {
    __shared__ __align__(16) float rawA[2][16 * SKM];
    __shared__ __align__(16) float rawB[2][16 * SBR];
    __shared__ uint4 pkA[PKA_SZ];
    __shared__ uint4 pkB[PKB_SZ];
    int d0 = blockIdx.x * 128, n = blockIdx.y;
    int t = threadIdx.x, wid = t >> 5, lane = t & 31;
    int gid = lane >> 2, tig = lane & 3;
    int wm = wid >> 1, wn = wid & 1;
    int rw = t >> 5, rt = lane >> 3, rg = lane & 7;
    const float* bb = g_B + (size_t)n * KTOT * LL;
    uint32_t sA[2] = {smem_u32(&rawA[0][0]), smem_u32(&rawA[1][0])};
    uint32_t sBm[2] = {smem_u32(&rawB[0][0]), smem_u32(&rawB[1][0])};
    float c[2][4][4] = {};

    int ar0 = t >> 5, ac4 = (t & 31) * 4;
    int br = t >> 4, bc4 = (t & 15) * 4;

    cpa16(sA[0] + (ar0 * SKM + ac4) * 4, g_wtokT + (size_t)ar0 * CTD + d0 + ac4);
    cpa16(sA[0] + ((ar0 + 8) * SKM + ac4) * 4, g_wtokT + (size_t)(ar0 + 8) * CTD + d0 + ac4);
    cpa16(sBm[0] + (br * SBR + bc4) * 4, bb + (size_t)br * LL + bc4);
    CPA_COMMIT();

    for (int s = 0; s < 36; ++s) {
        int buf = s & 1;
        if (s < 35) {
            int k1 = (s + 1) * 16, b1 = (s + 1) & 1;
            cpa16(sA[b1] + (ar0 * SKM + ac4) * 4, g_wtokT + (size_t)(k1 + ar0) * CTD + d0 + ac4);
            cpa16(sA[b1] + ((ar0 + 8) * SKM + ac4) * 4, g_wtokT + (size_t)(k1 + ar0 + 8) * CTD + d0 + ac4);
            cpa16(sBm[b1] + (br * SBR + bc4) * 4, bb + (size_t)(k1 + br) * LL + bc4);
            CPA_COMMIT();
            CPA_WAIT1();
        } else {
            CPA_WAIT0();
        }
        __syncthreads();
#pragma unroll
        for (int ks = 0; ks < 2; ++ks) {
            const float* Ra = rawA[buf];
            int kq = 8 * ks + rt, m = 16 * rw + rg;
            uint4 qa = make_uint4(__float_as_uint(Ra[kq * SKM + m]), __float_as_uint(Ra[kq * SKM + m + 8]),
                                  __float_as_uint(Ra[(kq + 4) * SKM + m]), __float_as_uint(Ra[(kq + 4) * SKM + m + 8]));
            pkA[(ks * 4 + rt) * PKA_T + rw * 8 + rg + 2 * rt] = qa;
        }
        REPACK_B(rawB[buf]);
        __syncthreads();
        MMA_PHASE();
    }
#pragma unroll
    for (int mi = 0; mi < 2; ++mi)
#pragma unroll
        for (int ni = 0; ni < 4; ++ni) {
            int col = wn * 32 + ni * 8 + tig * 2;
#pragma unroll
            for (int h = 0; h < 2; ++h) {
                int d = d0 + wm * 32 + mi * 16 + gid + h * 8;
                float bt = b_tok[d];
                float2 v = {c[mi][ni][h * 2] + bt, c[mi][ni][h * 2 + 1] + bt};
                *(float2*)(out + ((size_t)n * CTD + d) * LL + col) = v;
            }
        }
}

extern "C" void kernel_launch(void* const* d_in, const int* in_sizes, int n_in,
                              void* d_out, int out_size) {
    const float* feat  = (const float*)d_in[0];
    const float* w_tc  = (const float*)d_in[1];
    const float* b_tc  = (const float*)d_in[2];
    const float* w_val = (const float*)d_in[3];
    const float* b_val = (const float*)d_in[4];
    const float* w_ds3 = (const float*)d_in[5];
    const float* b_ds3 = (const float*)d_in[6];
    const float* w_ds1 = (const float*)d_in[7];
    const float* b_ds1 = (const float*)d_in[8];
    const float* w_pos = (const float*)d_in[9];
    const float* b_pos = (const float*)d_in[10];
    const float* w_tok = (const float*)d_in[11];
    const float* b_tok = (const float*)d_in[12];
    float* out = (float*)d_out;

    cudaFuncSetAttribute(k_logits_mma, cudaFuncAttributeMaxDynamicSharedMemorySize, K1_DYN);
    cudaFuncSetAttribute(k_agemm, cudaFuncAttributeMaxDynamicSharedMemorySize, K5_DYN);

    k_tr_wtc<<<128, 256>>>(w_tc);
    k_tr_wtok<<<1152, 256>>>(w_tok);
    k_logits_mma<<<dim3(NCH, 32), 256, K1_DYN>>>(feat, b_tc);
    k_agemm<<<dim3(4, 4, 32), 256, K5_DYN>>>(feat);
    k_pos<<<2048, 64>>>(w_ds3, b_ds3, w_ds1, b_ds1);
    k_mix<<<dim3(16, 32), 256>>>(w_val, b_val);
    k_posrows<<<32, 256>>>(w_pos, b_pos);
    k_final_mma<<<dim3(4, 32), 256>>>(b_tok, out);
}

// round 17
// speedup vs baseline: 1.3284x; 1.0671x over previous
#include <cuda_runtime.h>
#include <cstdint>

#define NB   32
#define CCH  512
#define HWD  3136
#define LL   64
#define CTD  512
#define KTOT 576   // 561 padded to 576
#define NCH  25    // softmax chunks = ceil(3136/128)

// -------- scratch (device globals; no runtime allocation) --------
__device__ float g_tc[(size_t)NB * HWD * LL];      // RAW scaled logits, layout (n, hw, l)
__device__ float g_part[NB * NCH * LL * 2];        // per-CTA online-softmax (m, s)
__device__ float g_Ap[4][(size_t)NB * CTD * LL];   // split-K partials of A (n, c, l)
__device__ float g_pcp[NB * LL * 49];              // pos-encoder conv output (n, l, 49)
__device__ float g_B[(size_t)NB * KTOT * LL];      // concat [tokens0; pos; zeros] (n, 576, l)
__device__ float g_wtcT[CCH * LL];                 // w_tc transposed (c, l), PRE-CONVERTED tf32 bits
__device__ float g_wtokT[KTOT * CTD];              // w_tok transposed + padded, PRE-CONVERTED tf32 bits

// -------- helpers --------
__device__ __forceinline__ unsigned f2tf(float x) {
    unsigned u; asm("cvt.rna.tf32.f32 %0, %1;" : "=r"(u) : "f"(x)); return u;
}
__device__ __forceinline__ void mma8(float* c, const unsigned* a, const unsigned* b) {
    asm volatile(
        "mma.sync.aligned.m16n8k8.row.col.f32.tf32.tf32.f32 "
        "{%0,%1,%2,%3},{%4,%5,%6,%7},{%8,%9},{%0,%1,%2,%3};"
        : "+f"(c[0]), "+f"(c[1]), "+f"(c[2]), "+f"(c[3])
        : "r"(a[0]), "r"(a[1]), "r"(a[2]), "r"(a[3]), "r"(b[0]), "r"(b[1]));
}
__device__ __forceinline__ uint32_t smem_u32(const void* p) {
    uint32_t a;
    asm("{ .reg .u64 t; cvta.to.shared.u64 t, %1; cvt.u32.u64 %0, t; }" : "=r"(a) : "l"(p));
    return a;
}
__device__ __forceinline__ void cpa16(uint32_t dst, const void* src) {
    asm volatile("cp.async.cg.shared.global [%0], [%1], 16;" :: "r"(dst), "l"(src));
}
#define CPA_COMMIT() asm volatile("cp.async.commit_group;" ::: "memory")
#define CPA_WAIT3()  asm volatile("cp.async.wait_group 3;" ::: "memory")
#define CPA_WAIT2()  asm volatile("cp.async.wait_group 2;" ::: "memory")
#define CPA_WAIT1()  asm volatile("cp.async.wait_group 1;" ::: "memory")
#define CPA_WAIT0()  asm volatile("cp.async.wait_group 0;" ::: "memory")
#define WAIT_LADDER(rem) do {                              \
    if ((rem) >= 3) CPA_WAIT3();                           \
    else if ((rem) == 2) CPA_WAIT2();                      \
    else if ((rem) == 1) CPA_WAIT1();                      \
    else CPA_WAIT0();                                      \
} while (0)

// -------- weight preprocessing (merged; pre-convert to tf32 bits) --------
__global__ void k_tr(const float* __restrict__ w_tc, const float* __restrict__ w_tok) {
    int b = blockIdx.x, t = threadIdx.x;
    if (b < 128) {
        int idx = b * 256 + t;                         // 32768
        int c = idx >> 6, l = idx & 63;
        g_wtcT[idx] = __uint_as_float(f2tf(w_tc[l * CCH + c]));
    } else {
        int idx = (b - 128) * 256 + t;                 // 294912
        int k = idx >> 9, d = idx & 511;
        g_wtokT[idx] = (k < 561) ? __uint_as_float(f2tf(w_tok[d * 561 + k])) : 0.0f;
    }
}

#define SA1 136   // K1 A stride, k-major: frag bank 8*tig+gid, conflict-free
#define SMM 20    // K5 A stride, m-major: frag bank 20*gid+tig -> all distinct, conflict-free
#define SBR 72    // B stride: frag bank 8*tig+gid, conflict-free
// k_final repack constants
#define SKM 136
#define PKA_T 72
#define PKB_T 40
#define PKA_SZ 576
#define PKB_SZ 320
#define REPACK_B(rawBbuf) do {                                                        \
    int ksb = rw & 1, qn = rw >> 1;                                                   \
    const float* Rb = (rawBbuf);                                                      \
    int k0 = 8 * ksb + rt, nn0 = 16 * qn + rg;                                        \
    uint4 qb = make_uint4(f2tf(Rb[k0 * SBR + nn0]),  f2tf(Rb[(k0 + 4) * SBR + nn0]),  \
                          f2tf(Rb[k0 * SBR + nn0 + 8]), f2tf(Rb[(k0 + 4) * SBR + nn0 + 8])); \
    pkB[(ksb * 4 + rt) * PKB_T + qn * 8 + rg + 2 * rt] = qb;                          \
} while (0)
#define MMA_PHASE() do {                                                              \
    _Pragma("unroll")                                                                 \
    for (int ks = 0; ks < 2; ++ks) {                                                  \
        uint4 af0 = pkA[(ks * 4 + tig) * PKA_T + (2 * wm + 0) * 8 + gid + 2 * tig];   \
        uint4 af1 = pkA[(ks * 4 + tig) * PKA_T + (2 * wm + 1) * 8 + gid + 2 * tig];   \
        uint4 bf0 = pkB[(ks * 4 + tig) * PKB_T + (2 * wn + 0) * 8 + gid + 2 * tig];   \
        uint4 bf1 = pkB[(ks * 4 + tig) * PKB_T + (2 * wn + 1) * 8 + gid + 2 * tig];   \
        unsigned b0[2] = {bf0.x, bf0.y}, b1[2] = {bf0.z, bf0.w};                      \
        unsigned b2[2] = {bf1.x, bf1.y}, b3[2] = {bf1.z, bf1.w};                      \
        mma8(c[0][0], (const unsigned*)&af0, b0);                                     \
        mma8(c[0][1], (const unsigned*)&af0, b1);                                     \
        mma8(c[0][2], (const unsigned*)&af0, b2);                                     \
        mma8(c[0][3], (const unsigned*)&af0, b3);                                     \
        mma8(c[1][0], (const unsigned*)&af1, b0);                                     \
        mma8(c[1][1], (const unsigned*)&af1, b1);                                     \
        mma8(c[1][2], (const unsigned*)&af1, b2);                                     \
        mma8(c[1][3], (const unsigned*)&af1, b3);                                     \
    }                                                                                 \
} while (0)

// -------- K1: logits + fused per-CTA softmax partials. Tile 128(hw)x64(l), K=512, depth-4 --------
#define K1_AB (16 * SA1)                  // 2176 floats per A buffer
#define K1_BB (16 * SBR)                  // 1152 floats per B buffer
#define K1_DYN ((4 * K1_AB + 4 * K1_BB) * 4)   // 53248 B
__global__ __launch_bounds__(256, 3) void k_logits_mma(const float* __restrict__ feat,
                                                       const float* __restrict__ b_tc) {
    extern __shared__ __align__(16) float dyn[];
    __shared__ float sm_m[4][64], sm_s[4][64];
    int m0 = blockIdx.x * 128, n = blockIdx.y;
    int t = threadIdx.x, wid = t >> 5, lane = t & 31;
    int gid = lane >> 2, tig = lane & 3;
    int wm = wid >> 1, wn = wid & 1;
    const float* fb = feat + (size_t)n * CCH * HWD;
    uint32_t sAb = smem_u32(dyn);
    uint32_t sBb = smem_u32(dyn + 4 * K1_AB);
    float c[2][4][4] = {};

    int ar0 = t >> 5, ac4 = (t & 31) * 4;
    int mg0 = m0 + ac4; if (mg0 > HWD - 4) mg0 = HWD - 4;
    int br = t >> 4, bc4 = (t & 15) * 4;

    auto issue = [&](int sl) {
        int b = sl & 3, kk = sl * 16;
        cpa16(sAb + (b * K1_AB + ar0 * SA1 + ac4) * 4, fb + (size_t)(kk + ar0) * HWD + mg0);
        cpa16(sAb + (b * K1_AB + (ar0 + 8) * SA1 + ac4) * 4, fb + (size_t)(kk + ar0 + 8) * HWD + mg0);
        cpa16(sBb + (b * K1_BB + br * SBR + bc4) * 4, g_wtcT + (size_t)(kk + br) * LL + bc4);
        CPA_COMMIT();
    };
    issue(0); issue(1); issue(2);

    for (int s = 0; s < 32; ++s) {
        int rem = 31 - s;
        if (rem >= 3) issue(s + 3);
        WAIT_LADDER(rem);
        __syncthreads();
        const float* Ab = dyn + (s & 3) * K1_AB;
        const float* Bb = dyn + 4 * K1_AB + (s & 3) * K1_BB;
#pragma unroll
        for (int ks = 0; ks < 2; ++ks) {
            int kb = ks * 8;
            unsigned a[2][4], b[4][2];
#pragma unroll
            for (int mi = 0; mi < 2; ++mi) {
                int r0 = wm * 32 + mi * 16 + gid;
                a[mi][0] = f2tf(Ab[(kb + tig) * SA1 + r0]);
                a[mi][1] = f2tf(Ab[(kb + tig) * SA1 + r0 + 8]);
                a[mi][2] = f2tf(Ab[(kb + tig + 4) * SA1 + r0]);
                a[mi][3] = f2tf(Ab[(kb + tig + 4) * SA1 + r0 + 8]);
            }
#pragma unroll
            for (int ni = 0; ni < 4; ++ni) {
                int nn = wn * 32 + ni * 8 + gid;
                b[ni][0] = __float_as_uint(Bb[(kb + tig) * SBR + nn]);       // pre-converted
                b[ni][1] = __float_as_uint(Bb[(kb + tig + 4) * SBR + nn]);
            }
#pragma unroll
            for (int mi = 0; mi < 2; ++mi)
#pragma unroll
                for (int ni = 0; ni < 4; ++ni) mma8(c[mi][ni], a[mi], b[ni]);
        }
        __syncthreads();
    }
    // ---- epilogue: store raw scaled logits + per-CTA online-softmax partials ----
    const float inv = 0.044194173824159216f;   // 1/sqrt(512)
    float* ob = g_tc + (size_t)n * HWD * LL;
    float bt0[4], bt1[4];
#pragma unroll
    for (int ni = 0; ni < 4; ++ni) {
        int col = wn * 32 + ni * 8 + tig * 2;
        bt0[ni] = b_tc[col]; bt1[ni] = b_tc[col + 1];
    }
    float m8[4][2], s8[4][2];
#pragma unroll
    for (int ni = 0; ni < 4; ++ni) { m8[ni][0] = m8[ni][1] = -1e30f; s8[ni][0] = s8[ni][1] = 0.0f; }
#pragma unroll
    for (int mi = 0; mi < 2; ++mi)
#pragma unroll
        for (int ni = 0; ni < 4; ++ni) {
            int col = wn * 32 + ni * 8 + tig * 2;
#pragma unroll
            for (int h = 0; h < 2; ++h) {
                int hw = m0 + wm * 32 + mi * 16 + gid + h * 8;
                if (hw < HWD) {
                    float v0 = (c[mi][ni][h * 2] + bt0[ni]) * inv;
                    float v1 = (c[mi][ni][h * 2 + 1] + bt1[ni]) * inv;
                    *(float2*)(ob + (size_t)hw * LL + col) = make_float2(v0, v1);
                    m8[ni][0] = fmaxf(m8[ni][0], v0);
                    m8[ni][1] = fmaxf(m8[ni][1], v1);
                }
            }
        }
#pragma unroll
    for (int ni = 0; ni < 4; ++ni)
#pragma unroll
        for (int q = 0; q < 2; ++q) {
            float m = m8[ni][q];
            m = fmaxf(m, __shfl_xor_sync(~0u, m, 4));
            m = fmaxf(m, __shfl_xor_sync(~0u, m, 8));
            m = fmaxf(m, __shfl_xor_sync(~0u, m, 16));
            m8[ni][q] = m;
        }
#pragma unroll
    for (int mi = 0; mi < 2; ++mi)
#pragma unroll
        for (int ni = 0; ni < 4; ++ni)
#pragma unroll
            for (int h = 0; h < 2; ++h) {
                int hw = m0 + wm * 32 + mi * 16 + gid + h * 8;
                if (hw < HWD) {
                    float v0 = (c[mi][ni][h * 2] + bt0[ni]) * inv;
                    float v1 = (c[mi][ni][h * 2 + 1] + bt1[ni]) * inv;
                    s8[ni][0] += __expf(v0 - m8[ni][0]);
                    s8[ni][1] += __expf(v1 - m8[ni][1]);
                }
            }
#pragma unroll
    for (int ni = 0; ni < 4; ++ni)
#pragma unroll
        for (int q = 0; q < 2; ++q) {
            float s = s8[ni][q];
            s += __shfl_xor_sync(~0u, s, 4);
            s += __shfl_xor_sync(~0u, s, 8);
            s += __shfl_xor_sync(~0u, s, 16);
            s8[ni][q] = s;
        }
    if (gid == 0) {
#pragma unroll
        for (int ni = 0; ni < 4; ++ni)
#pragma unroll
            for (int q = 0; q < 2; ++q) {
                int l = wn * 32 + ni * 8 + tig * 2 + q;
                sm_m[wm][l] = m8[ni][q];
                sm_s[wm][l] = s8[ni][q];
            }
    }
    __syncthreads();
    if (t < 64) {
        float M = sm_m[0][t], S = sm_s[0][t];
#pragma unroll
        for (int w = 1; w < 4; ++w) {
            float m2 = sm_m[w][t], s2 = sm_s[w][t];
            float nm = fmaxf(M, m2);
            S = S * __expf(M - nm) + s2 * __expf(m2 - nm);
            M = nm;
        }
        g_part[((n * NCH + blockIdx.x) * 64 + t) * 2 + 0] = M;
        g_part[((n * NCH + blockIdx.x) * 64 + t) * 2 + 1] = S;
    }
}

// -------- K5: A = sum_hw feat * softmax(logits); transform(s+1) hidden in MMA(s) window; depth-4 --------
#define K5_AB (128 * SMM)                 // 2560 floats per A buffer
#define K5_BB (16 * SBR)                  // 1152 floats per B buffer
#define K5_DYN ((4 * K5_AB + 4 * K5_BB) * 4)   // 59392 B
__global__ __launch_bounds__(256, 3) void k_agemm(const float* __restrict__ feat) {
    extern __shared__ __align__(16) float dyn[];
    __shared__ float sM[64], sI[64];
    int c0 = blockIdx.x * 128, part = blockIdx.y, n = 31 - blockIdx.z;
    int hwb = part * 784;
    int t = threadIdx.x, wid = t >> 5, lane = t & 31;
    int gid = lane >> 2, tig = lane & 3;
    int wm = wid >> 1, wn = wid & 1;
    const float* fa = feat + ((size_t)n * CCH + c0) * HWD + hwb;
    const float* tb = g_tc + ((size_t)n * HWD + hwb) * LL;
    uint32_t sAb = smem_u32(dyn);
    uint32_t sBb = smem_u32(dyn + 4 * K5_AB);
    float c[2][4][4] = {};

    int am = t >> 1, ak = (t & 1) * 8;
    int br = t >> 4, bc4 = (t & 15) * 4;

    auto issue = [&](int sl) {
        int b = sl & 3, kk = sl * 16;
        cpa16(sAb + (b * K5_AB + am * SMM + ak) * 4, fa + (size_t)am * HWD + kk + ak);
        cpa16(sAb + (b * K5_AB + am * SMM + ak + 4) * 4, fa + (size_t)am * HWD + kk + ak + 4);
        cpa16(sBb + (b * K5_BB + br * SBR + bc4) * 4, tb + (size_t)(kk + br) * LL + bc4);
        CPA_COMMIT();
    };
    issue(0); issue(1); issue(2);

    // folded softmax merge (overlaps first slabs in flight)
    if (t < 64) {
        float M = -1e30f, S = 0.0f;
#pragma unroll
        for (int ch = 0; ch < NCH; ++ch) {
            float m = g_part[((n * NCH + ch) * 64 + t) * 2 + 0];
            float s = g_part[((n * NCH + ch) * 64 + t) * 2 + 1];
            float nm = fmaxf(M, m);
            S = S * __expf(M - nm) + s * __expf(m - nm);
            M = nm;
        }
        sM[t] = M;
        sI[t] = 1.0f / S;
    }

    // prologue: slabs 0,1 arrived; transform B[0]
    CPA_WAIT1();
    __syncthreads();
    {
        float* B0 = dyn + 4 * K5_AB;
#pragma unroll
        for (int j = 0; j < 4; ++j) {
            int l = bc4 + j;
            B0[br * SBR + l] = __uint_as_float(f2tf(__expf(B0[br * SBR + l] - sM[l]) * sI[l]));
        }
    }
    __syncthreads();

    for (int s = 0; s < 49; ++s) {
        if (s + 3 <= 48) { issue(s + 3); CPA_WAIT2(); }
        else if (s == 46) CPA_WAIT1();
        else CPA_WAIT0();
        __syncthreads();                 // sync1: slab s+1 data + prior MMA done
        const float* Ab = dyn + (s & 3) * K5_AB;
        const float* Bcur = dyn + 4 * K5_AB + (s & 3) * K5_BB;
        if (s + 1 < 49) {                // transform next slab's B, overlapped with MMA below
            float* Bnx = dyn + 4 * K5_AB + ((s + 1) & 3) * K5_BB;
#pragma unroll
            for (int j = 0; j < 4; ++j) {
                int l = bc4 + j;
                Bnx[br * SBR + l] = __uint_as_float(f2tf(__expf(Bnx[br * SBR + l] - sM[l]) * sI[l]));
            }
        }
#pragma unroll
        for (int ks = 0; ks < 2; ++ks) {
            int kb = ks * 8;
            unsigned a[2][4], b[4][2];
#pragma unroll
            for (int mi = 0; mi < 2; ++mi) {
                int r0 = wm * 32 + mi * 16 + gid;
                a[mi][0] = f2tf(Ab[r0 * SMM + kb + tig]);
                a[mi][1] = f2tf(Ab[(r0 + 8) * SMM + kb + tig]);
                a[mi][2] = f2tf(Ab[r0 * SMM + kb + tig + 4]);
                a[mi][3] = f2tf(Ab[(r0 + 8) * SMM + kb + tig + 4]);
            }
#pragma unroll
            for (int ni = 0; ni < 4; ++ni) {
                int nn = wn * 32 + ni * 8 + gid;
                b[ni][0] = __float_as_uint(Bcur[(kb + tig) * SBR + nn]);     // pre-converted
                b[ni][1] = __float_as_uint(Bcur[(kb + tig + 4) * SBR + nn]);
            }
#pragma unroll
            for (int mi = 0; mi < 2; ++mi)
#pragma unroll
                for (int ni = 0; ni < 4; ++ni) mma8(c[mi][ni], a[mi], b[ni]);
        }
        __syncthreads();                 // sync2: MMA + transform done before buffer reuse
    }
    float* ob = g_Ap[part] + ((size_t)n * CTD + c0) * LL;
#pragma unroll
    for (int mi = 0; mi < 2; ++mi)
#pragma unroll
        for (int ni = 0; ni < 4; ++ni) {
            int col = wn * 32 + ni * 8 + tig * 2;
#pragma unroll
            for (int h = 0; h < 2; ++h) {
                int row = wm * 32 + mi * 16 + gid + h * 8;
                float2 v = {c[mi][ni][h * 2], c[mi][ni][h * 2 + 1]};
                *(float2*)(ob + (size_t)row * LL + col) = v;
            }
        }
}

// -------- K6: pos-encoder; computes its own (n,l) softmax merge from g_part --------
__global__ void k_pos(const float* __restrict__ w_ds3, const float* __restrict__ b_ds3,
                      const float* __restrict__ w_ds1, const float* __restrict__ b_ds1) {
    int nl = blockIdx.x;                         // n*64 + l
    int n = nl >> 6, l = nl & 63;
    __shared__ float S[196];
    __shared__ float sMI[2];
    int t = threadIdx.x, lane = t & 31;
    if (t < 32) {
        float m = -1e30f, s = 0.0f;
        if (lane < NCH) {
            m = g_part[((n * NCH + lane) * 64 + l) * 2 + 0];
            s = g_part[((n * NCH + lane) * 64 + l) * 2 + 1];
        }
        float M = m;
#pragma unroll
        for (int o = 16; o; o >>= 1) M = fmaxf(M, __shfl_xor_sync(~0u, M, o));
        s *= __expf(m - M);
#pragma unroll
        for (int o = 16; o; o >>= 1) s += __shfl_xor_sync(~0u, s, o);
        if (lane == 0) { sMI[0] = M; sMI[1] = 1.0f / s; }
    }
    __syncthreads();
    float M = sMI[0], I = sMI[1];
    const float* base = g_tc + (size_t)n * HWD * LL + (size_t)l * HWD;  // flat view slice
    for (int q = t; q < 196; q += 64) {
        int i = q / 14, j = q % 14;
        S[q] = __expf(base[i * 224 + j * 4] - M) * I;
    }
    __syncthreads();
    if (t < 49) {
        int oy = t / 7, ox = t % 7;
        float acc = 0.0f;
#pragma unroll
        for (int ky = 0; ky < 3; ++ky)
#pragma unroll
            for (int kx = 0; kx < 3; ++kx) {
                int iy = 2 * oy + ky - 1, ix = 2 * ox + kx - 1;
                if (iy >= 0 && iy < 14 && ix >= 0 && ix < 14)
                    acc += S[iy * 14 + ix] * w_ds3[ky * 3 + kx];
            }
        float v = (acc + b_ds3[0]) * w_ds1[0] + b_ds1[0];
        g_pcp[(size_t)nl * 49 + t] = v;
    }
}

// -------- K7 (merged): blocks [0,512) grouped mix; blocks [512,544) pos rows --------
__global__ __launch_bounds__(256) void k_mixpos(const float* __restrict__ w_val,
                                                const float* __restrict__ b_val,
                                                const float* __restrict__ w_pos,
                                                const float* __restrict__ b_pos) {
    __shared__ float buf[5537];
    int blk = blockIdx.x, t = threadIdx.x;
    if (blk < 512) {
        int g = blk & 15, n = blk >> 4;
        float* sA = buf;              // [32][64] flat
        float* sW = buf + 2048;       // [32][33] flat
        size_t abase = ((size_t)n * CTD + g * 32) * LL;
        for (int q = t; q < 2048; q += 256) {
            float v = g_Ap[0][abase + q] + g_Ap[1][abase + q] +
                      g_Ap[2][abase + q] + g_Ap[3][abase + q];
            sA[q] = v;
        }
        for (int q = t; q < 1024; q += 256) sW[(q >> 5) * 33 + (q & 31)] = w_val[g * 1024 + q];
        __syncthreads();
        for (int q = t; q < 2048; q += 256) {
            int d = q >> 6, l = q & 63;
            float acc = b_val[g * 32 + d];      // sum_hw tc == 1 exactly
#pragma unroll
            for (int c = 0; c < 32; ++c) acc += sW[d * 33 + c] * sA[c * 64 + l];
            g_B[((size_t)n * KTOT + g * 32 + d) * LL + l] = acc;
        }
    } else {
        int n = blk - 512;
        float* sp = buf;              // (l,49)
        float* swp = buf + 3136;
        for (int q = t; q < 3136; q += 256) sp[q] = g_pcp[(size_t)n * 3136 + q];
        for (int q = t; q < 2401; q += 256) swp[q] = w_pos[q];
        __syncthreads();
        for (int q = t; q < 4096; q += 256) {
            int p = q >> 6, l = q & 63;
            float v = 0.0f;
            if (p < 49) {
                v = b_pos[p];
                for (int c = 0; c < 49; ++c) v += swp[p * 49 + c] * sp[l * 49 + c];
            }
            g_B[((size_t)n * KTOT + 512 + p) * LL + l] = v;
        }
    }
}

// -------- K8 (tf32 MMA): out[n,d,l] = wtokT^T @ B + b_tok. Tile 128(d)x64(l), K=576 --------
__global__ __launch_bounds__(256) void k_final_mma(const float* __restrict__ b_tok,
                                                   float* __restrict__ out) {
    __shared__ __align__(16) float rawA[2][16 * SKM];
    __shared__ __align__(16) float rawB[2][16 * SBR];
    __shared__ uint4 pkA[PKA_SZ];
    __shared__ uint4 pkB[PKB_SZ];
    int d0 = blockIdx.x * 128, n = blockIdx.y;
    int t = threadIdx.x, wid = t >> 5, lane = t & 31;
    int gid = lane >> 2, tig = lane & 3;
    int wm = wid >> 1, wn = wid & 1;
    int rw = t >> 5, rt = lane >> 3, rg = lane & 7;
    const float* bb = g_B + (size_t)n * KTOT * LL;
    uint32_t sA[2] = {smem_u32(&rawA[0][0]), smem_u32(&rawA[1][0])};
    uint32_t sBm[2] = {smem_u32(&rawB[0][0]), smem_u32(&rawB[1][0])};
    float c[2][4][4] = {};

    int ar0 = t >> 5, ac4 = (t & 31) * 4;
    int br = t >> 4, bc4 = (t & 15) * 4;

    cpa16(sA[0] + (ar0 * SKM + ac4) * 4, g_wtokT + (size_t)ar0 * CTD + d0 + ac4);
    cpa16(sA[0] + ((ar0 + 8) * SKM + ac4) * 4, g_wtokT + (size_t)(ar0 + 8) * CTD + d0 + ac4);
    cpa16(sBm[0] + (br * SBR + bc4) * 4, bb + (size_t)br * LL + bc4);
    CPA_COMMIT();

    for (int s = 0; s < 36; ++s) {
        int buf = s & 1;
        if (s < 35) {
            int k1 = (s + 1) * 16, b1 = (s + 1) & 1;
            cpa16(sA[b1] + (ar0 * SKM + ac4) * 4, g_wtokT + (size_t)(k1 + ar0) * CTD + d0 + ac4);
            cpa16(sA[b1] + ((ar0 + 8) * SKM + ac4) * 4, g_wtokT + (size_t)(k1 + ar0 + 8) * CTD + d0 + ac4);
            cpa16(sBm[b1] + (br * SBR + bc4) * 4, bb + (size_t)(k1 + br) * LL + bc4);
            CPA_COMMIT();
            CPA_WAIT1();
        } else {
            CPA_WAIT0();
        }
        __syncthreads();
#pragma unroll
        for (int ks = 0; ks < 2; ++ks) {
            const float* Ra = rawA[buf];
            int kq = 8 * ks + rt, m = 16 * rw + rg;
            uint4 qa = make_uint4(__float_as_uint(Ra[kq * SKM + m]), __float_as_uint(Ra[kq * SKM + m + 8]),
                                  __float_as_uint(Ra[(kq + 4) * SKM + m]), __float_as_uint(Ra[(kq + 4) * SKM + m + 8]));
            pkA[(ks * 4 + rt) * PKA_T + rw * 8 + rg + 2 * rt] = qa;
        }
        REPACK_B(rawB[buf]);
        __syncthreads();
        MMA_PHASE();
    }
#pragma unroll
    for (int mi = 0; mi < 2; ++mi)
#pragma unroll
        for (int ni = 0; ni < 4; ++ni) {
            int col = wn * 32 + ni * 8 + tig * 2;
#pragma unroll
            for (int h = 0; h < 2; ++h) {
                int d = d0 + wm * 32 + mi * 16 + gid + h * 8;
                float bt = b_tok[d];
                float2 v = {c[mi][ni][h * 2] + bt, c[mi][ni][h * 2 + 1] + bt};
                *(float2*)(out + ((size_t)n * CTD + d) * LL + col) = v;
            }
        }
}

extern "C" void kernel_launch(void* const* d_in, const int* in_sizes, int n_in,
                              void* d_out, int out_size) {
    const float* feat  = (const float*)d_in[0];
    const float* w_tc  = (const float*)d_in[1];
    const float* b_tc  = (const float*)d_in[2];
    const float* w_val = (const float*)d_in[3];
    const float* b_val = (const float*)d_in[4];
    const float* w_ds3 = (const float*)d_in[5];
    const float* b_ds3 = (const float*)d_in[6];
    const float* w_ds1 = (const float*)d_in[7];
    const float* b_ds1 = (const float*)d_in[8];
    const float* w_pos = (const float*)d_in[9];
    const float* b_pos = (const float*)d_in[10];
    const float* w_tok = (const float*)d_in[11];
    const float* b_tok = (const float*)d_in[12];
    float* out = (float*)d_out;

    cudaFuncSetAttribute(k_logits_mma, cudaFuncAttributeMaxDynamicSharedMemorySize, K1_DYN);
    cudaFuncSetAttribute(k_agemm, cudaFuncAttributeMaxDynamicSharedMemorySize, K5_DYN);

    k_tr<<<1280, 256>>>(w_tc, w_tok);
    k_logits_mma<<<dim3(NCH, 32), 256, K1_DYN>>>(feat, b_tc);
    k_agemm<<<dim3(4, 4, 32), 256, K5_DYN>>>(feat);
    k_pos<<<2048, 64>>>(w_ds3, b_ds3, w_ds1, b_ds1);
    k_mixpos<<<544, 256>>>(w_val, b_val, w_pos, b_pos);
    k_final_mma<<<dim3(4, 32), 256>>>(b_tok, out);
}